// round 4
// baseline (speedup 1.0000x reference)
#include <cuda_runtime.h>

// SKA forward: out[b, g*16+cg, h, w] = sum_{k=0..8} x_pad[b, g*16+cg, h+di, w+dj] * w[b, cg, k, h, w]
// x (16,512,56,56) f32, w (16,16,9,56,56) f32, out (16,512,56,56) f32.
// Thread owns (b, gs, cg, h, w4): 9 weight float4 in regs, loops over 16 groups
// (GSPLIT=2) with unroll-4 for deep MLP. Horizontal halo via warp shuffle;
// row-wrap lanes coincide with image edges (zero), warp-edge lanes do a
// predicated scalar load.

#define NB   16
#define NC   512
#define NG   32
#define NCG  16
#define NH   56
#define NW   56
#define NW4  14            // 56 / 4
#define PLANE   (NH * NW)  // 3136
#define GSPLIT  2
#define GPT     (NG / GSPLIT)   // 16 groups per thread
#define CSTRIDE (NCG * PLANE)   // stride between consecutive groups (same cg)

__global__ __launch_bounds__(128, 8) void ska_kernel(
    const float* __restrict__ x,
    const float* __restrict__ wt,
    float* __restrict__ out)
{
    const int idx = blockIdx.x * 128 + threadIdx.x;
    const int lane = threadIdx.x & 31;
    // idx = (((b*GSPLIT + gs)*NCG + cg)*NH + h)*NW4 + w4
    const int w4 = idx % NW4;
    int t        = idx / NW4;
    const int h  = t % NH;  t /= NH;
    const int cg = t % NCG; t /= NCG;
    const int gs = t % GSPLIT;
    const int b  = t / GSPLIT;
    const int col = w4 * 4;

    // ---- 9 weight float4s, reused across the 16 groups ----
    const float* wbase = wt + ((((b * NCG + cg) * 9) * NH + h) * NW + col);
    float4 wk[9];
#pragma unroll
    for (int k = 0; k < 9; ++k)
        wk[k] = *reinterpret_cast<const float4*>(wbase + k * PLANE);

    const bool hm = (h > 0);
    const bool hp = (h < NH - 1);
    const bool wl = (col > 0);
    const bool wr = (col < NW - 4);

    const int base = (b * NC + (gs * GPT) * NCG + cg) * PLANE + h * NW + col;
    const float* xc = x + base;
    float* oc       = out + base;

#pragma unroll 4
    for (int j = 0; j < GPT; ++j) {
        const float* xp = xc;
        xc += CSTRIDE;
        float4 a = make_float4(0.f, 0.f, 0.f, 0.f);

#pragma unroll
        for (int di = 0; di < 3; ++di) {
            const bool v = (di == 1) || (di == 0 && hm) || (di == 2 && hp);
            const float* row = xp + (di - 1) * NW;

            float4 xm = make_float4(0.f, 0.f, 0.f, 0.f);
            if (v) xm = *reinterpret_cast<const float4*>(row);

            // horizontal halo via shuffle (all lanes participate)
            float xl = __shfl_up_sync(0xffffffffu,  xm.w, 1);
            float xr = __shfl_down_sync(0xffffffffu, xm.x, 1);
            // warp-edge lanes mid-row: real load (predicated, <=2 lanes active)
            if (lane == 0  && wl) xl = v ? row[-1] : 0.f;
            if (lane == 31 && wr) xr = v ? row[4]  : 0.f;
            // image edges: halo is zero
            if (!wl) xl = 0.f;
            if (!wr) xr = 0.f;

            const float4 w0 = wk[di * 3 + 0];
            const float4 w1 = wk[di * 3 + 1];
            const float4 w2 = wk[di * 3 + 2];

            // dj = -1
            a.x = fmaf(xl,   w0.x, a.x);
            a.y = fmaf(xm.x, w0.y, a.y);
            a.z = fmaf(xm.y, w0.z, a.z);
            a.w = fmaf(xm.z, w0.w, a.w);
            // dj = 0
            a.x = fmaf(xm.x, w1.x, a.x);
            a.y = fmaf(xm.y, w1.y, a.y);
            a.z = fmaf(xm.z, w1.z, a.z);
            a.w = fmaf(xm.w, w1.w, a.w);
            // dj = +1
            a.x = fmaf(xm.y, w2.x, a.x);
            a.y = fmaf(xm.z, w2.y, a.y);
            a.z = fmaf(xm.w, w2.z, a.z);
            a.w = fmaf(xr,   w2.w, a.w);
        }

        __stcs(reinterpret_cast<float4*>(oc), a);
        oc += CSTRIDE;
    }
}

extern "C" void kernel_launch(void* const* d_in, const int* in_sizes, int n_in,
                              void* d_out, int out_size)
{
    const float* x  = (const float*)d_in[0];
    const float* wt = (const float*)d_in[1];
    float* out      = (float*)d_out;

    const int total  = NB * GSPLIT * NCG * NH * NW4; // 401408 threads
    const int blocks = total / 128;                  // 3136
    ska_kernel<<<blocks, 128>>>(x, wt, out);
}

// round 5
// speedup vs baseline: 1.2963x; 1.2963x over previous
#include <cuda_runtime.h>

// SKA forward: out[b, g*16+cg, h, w] = sum_{k=0..8} x_pad[b, g*16+cg, h+di, w+dj] * w[b, cg, k, h, w]
// x (16,512,56,56) f32, w (16,16,9,56,56) f32, out (16,512,56,56) f32.
// R3 structure (best), GSPLIT=8: thread owns (b, gs, cg, h, w4), 9 weight
// float4 in regs, loops over 4 groups. Horizontal halo via warp shuffle;
// row-wrap lanes coincide with image edges (zero), warp-edge lanes do a
// predicated scalar load.

#define NB   16
#define NC   512
#define NG   32
#define NCG  16
#define NH   56
#define NW   56
#define NW4  14            // 56 / 4
#define PLANE   (NH * NW)  // 3136
#define GSPLIT  8
#define GPT     (NG / GSPLIT)   // 4 groups per thread
#define CSTRIDE (NCG * PLANE)   // stride between consecutive groups (same cg)

__global__ __launch_bounds__(128, 8) void ska_kernel(
    const float* __restrict__ x,
    const float* __restrict__ wt,
    float* __restrict__ out)
{
    const int idx = blockIdx.x * 128 + threadIdx.x;
    const int lane = threadIdx.x & 31;
    // idx = (((b*GSPLIT + gs)*NCG + cg)*NH + h)*NW4 + w4
    const int w4 = idx % NW4;
    int t        = idx / NW4;
    const int h  = t % NH;  t /= NH;
    const int cg = t % NCG; t /= NCG;
    const int gs = t % GSPLIT;
    const int b  = t / GSPLIT;
    const int col = w4 * 4;

    // ---- 9 weight float4s, reused across the 4 groups ----
    const float* wbase = wt + ((((b * NCG + cg) * 9) * NH + h) * NW + col);
    float4 wk[9];
#pragma unroll
    for (int k = 0; k < 9; ++k)
        wk[k] = *reinterpret_cast<const float4*>(wbase + k * PLANE);

    const bool hm = (h > 0);
    const bool hp = (h < NH - 1);
    const bool wl = (col > 0);
    const bool wr = (col < NW - 4);

    const int base = (b * NC + (gs * GPT) * NCG + cg) * PLANE + h * NW + col;
    const float* xc = x + base;
    float* oc       = out + base;

#pragma unroll 2
    for (int j = 0; j < GPT; ++j) {
        const float* xp = xc + j * CSTRIDE;
        float4 a = make_float4(0.f, 0.f, 0.f, 0.f);

#pragma unroll
        for (int di = 0; di < 3; ++di) {
            const bool v = (di == 1) || (di == 0 && hm) || (di == 2 && hp);
            const float* row = xp + (di - 1) * NW;

            float4 xm = make_float4(0.f, 0.f, 0.f, 0.f);
            if (v) xm = *reinterpret_cast<const float4*>(row);

            // horizontal halo via shuffle (all lanes participate)
            float xl = __shfl_up_sync(0xffffffffu,  xm.w, 1);
            float xr = __shfl_down_sync(0xffffffffu, xm.x, 1);
            // warp-edge lanes mid-row: real load (predicated, <=2 lanes active)
            if (lane == 0  && wl) xl = v ? row[-1] : 0.f;
            if (lane == 31 && wr) xr = v ? row[4]  : 0.f;
            // image edges: halo is zero
            if (!wl) xl = 0.f;
            if (!wr) xr = 0.f;

            const float4 w0 = wk[di * 3 + 0];
            const float4 w1 = wk[di * 3 + 1];
            const float4 w2 = wk[di * 3 + 2];

            // dj = -1
            a.x = fmaf(xl,   w0.x, a.x);
            a.y = fmaf(xm.x, w0.y, a.y);
            a.z = fmaf(xm.y, w0.z, a.z);
            a.w = fmaf(xm.z, w0.w, a.w);
            // dj = 0
            a.x = fmaf(xm.x, w1.x, a.x);
            a.y = fmaf(xm.y, w1.y, a.y);
            a.z = fmaf(xm.z, w1.z, a.z);
            a.w = fmaf(xm.w, w1.w, a.w);
            // dj = +1
            a.x = fmaf(xm.y, w2.x, a.x);
            a.y = fmaf(xm.z, w2.y, a.y);
            a.z = fmaf(xm.w, w2.z, a.z);
            a.w = fmaf(xr,   w2.w, a.w);
        }

        __stcs(reinterpret_cast<float4*>(oc + j * CSTRIDE), a);
    }
}

extern "C" void kernel_launch(void* const* d_in, const int* in_sizes, int n_in,
                              void* d_out, int out_size)
{
    const float* x  = (const float*)d_in[0];
    const float* wt = (const float*)d_in[1];
    float* out      = (float*)d_out;

    const int total  = NB * GSPLIT * NCG * NH * NW4; // 1605632 threads
    const int blocks = total / 128;                  // 12544
    ska_kernel<<<blocks, 128>>>(x, wt, out);
}

// round 6
// speedup vs baseline: 1.3031x; 1.0052x over previous
#include <cuda_runtime.h>

// SKA forward: out[b, g*16+cg, h, w] = sum_{k=0..8} x_pad[b, g*16+cg, h+di, w+dj] * w[b, cg, k, h, w]
// x (16,512,56,56) f32, w (16,16,9,56,56) f32, out (16,512,56,56) f32.
// R6: di-outer / group-inner loop interchange. Only 3 weight float4s live at a
// time (12 regs vs 36), GPT=4 accumulators (16 regs) -> ~50 live regs, raising
// the occupancy ceiling to 62.5%. Memory traffic identical to R5.
// Horizontal halo via warp shuffle; row-wrap lanes coincide with image edges
// (zero), warp-edge lanes (0,31) do a predicated scalar load.

#define NB   16
#define NC   512
#define NG   32
#define NCG  16
#define NH   56
#define NW   56
#define NW4  14            // 56 / 4
#define PLANE   (NH * NW)  // 3136
#define GSPLIT  8
#define GPT     (NG / GSPLIT)   // 4 groups per thread
#define CSTRIDE (NCG * PLANE)   // stride between consecutive groups (same cg)

__global__ __launch_bounds__(128, 10) void ska_kernel(
    const float* __restrict__ x,
    const float* __restrict__ wt,
    float* __restrict__ out)
{
    const int idx = blockIdx.x * 128 + threadIdx.x;
    const int lane = threadIdx.x & 31;
    // idx = (((b*GSPLIT + gs)*NCG + cg)*NH + h)*NW4 + w4
    const int w4 = idx % NW4;
    int t        = idx / NW4;
    const int h  = t % NH;  t /= NH;
    const int cg = t % NCG; t /= NCG;
    const int gs = t % GSPLIT;
    const int b  = t / GSPLIT;
    const int col = w4 * 4;

    const bool hm = (h > 0);
    const bool hp = (h < NH - 1);
    const bool wl = (col > 0);
    const bool wr = (col < NW - 4);

    const float* wb = wt + ((((b * NCG + cg) * 9) * NH + h) * NW + col);
    const int base  = (b * NC + (gs * GPT) * NCG + cg) * PLANE + h * NW + col;
    const float* xb = x + base;
    float* ob       = out + base;

    float4 acc[GPT];
#pragma unroll
    for (int j = 0; j < GPT; ++j)
        acc[j] = make_float4(0.f, 0.f, 0.f, 0.f);

#pragma unroll
    for (int di = 0; di < 3; ++di) {
        const bool v = (di == 1) || (di == 0 && hm) || (di == 2 && hp);

        // only 3 weight float4s live per di-step
        const float4 w0 = *reinterpret_cast<const float4*>(wb + (di * 3 + 0) * PLANE);
        const float4 w1 = *reinterpret_cast<const float4*>(wb + (di * 3 + 1) * PLANE);
        const float4 w2 = *reinterpret_cast<const float4*>(wb + (di * 3 + 2) * PLANE);

#pragma unroll
        for (int j = 0; j < GPT; ++j) {
            const float* row = xb + (j * CSTRIDE + (di - 1) * NW); // immediate offsets

            float4 xm = make_float4(0.f, 0.f, 0.f, 0.f);
            if (v) xm = *reinterpret_cast<const float4*>(row);

            // horizontal halo via shuffle (all lanes participate)
            float xl = __shfl_up_sync(0xffffffffu,  xm.w, 1);
            float xr = __shfl_down_sync(0xffffffffu, xm.x, 1);
            // warp-edge lanes mid-row: real load (predicated, <=2 lanes active)
            if (lane == 0  && wl) xl = v ? row[-1] : 0.f;
            if (lane == 31 && wr) xr = v ? row[4]  : 0.f;
            // image edges: halo is zero
            if (!wl) xl = 0.f;
            if (!wr) xr = 0.f;

            // dj = -1
            acc[j].x = fmaf(xl,   w0.x, acc[j].x);
            acc[j].y = fmaf(xm.x, w0.y, acc[j].y);
            acc[j].z = fmaf(xm.y, w0.z, acc[j].z);
            acc[j].w = fmaf(xm.z, w0.w, acc[j].w);
            // dj = 0
            acc[j].x = fmaf(xm.x, w1.x, acc[j].x);
            acc[j].y = fmaf(xm.y, w1.y, acc[j].y);
            acc[j].z = fmaf(xm.z, w1.z, acc[j].z);
            acc[j].w = fmaf(xm.w, w1.w, acc[j].w);
            // dj = +1
            acc[j].x = fmaf(xm.y, w2.x, acc[j].x);
            acc[j].y = fmaf(xm.z, w2.y, acc[j].y);
            acc[j].z = fmaf(xm.w, w2.z, acc[j].z);
            acc[j].w = fmaf(xr,   w2.w, acc[j].w);
        }
    }

#pragma unroll
    for (int j = 0; j < GPT; ++j)
        __stcs(reinterpret_cast<float4*>(ob + j * CSTRIDE), acc[j]);
}

extern "C" void kernel_launch(void* const* d_in, const int* in_sizes, int n_in,
                              void* d_out, int out_size)
{
    const float* x  = (const float*)d_in[0];
    const float* wt = (const float*)d_in[1];
    float* out      = (float*)d_out;

    const int total  = NB * GSPLIT * NCG * NH * NW4; // 1605632 threads
    const int blocks = total / 128;                  // 12544
    ska_kernel<<<blocks, 128>>>(x, wt, out);
}

// round 7
// speedup vs baseline: 1.3956x; 1.0710x over previous
#include <cuda_runtime.h>

// SKA forward: out[b, g*16+cg, h, w] = sum_{k=0..8} x_pad[b, g*16+cg, h+di, w+dj] * w[b, cg, k, h, w]
// x (16,512,56,56) f32, w (16,16,9,56,56) f32, out (16,512,56,56) f32.
// R7: di-outer, phase-separated per di-step: [7 batched LDG.128] -> [8 SHFL]
// -> [48 FFMA]. Explicit xm[GPT] keeps loads consumer-free so ptxas
// front-batches them (MLP ~7/warp). 64-reg budget (launch_bounds 128,8).

#define NB   16
#define NC   512
#define NG   32
#define NCG  16
#define NH   56
#define NW   56
#define NW4  14            // 56 / 4
#define PLANE   (NH * NW)  // 3136
#define GSPLIT  8
#define GPT     (NG / GSPLIT)   // 4 groups per thread
#define CSTRIDE (NCG * PLANE)   // stride between consecutive groups (same cg)

__global__ __launch_bounds__(128, 8) void ska_kernel(
    const float* __restrict__ x,
    const float* __restrict__ wt,
    float* __restrict__ out)
{
    const int idx = blockIdx.x * 128 + threadIdx.x;
    const int lane = threadIdx.x & 31;
    // idx = (((b*GSPLIT + gs)*NCG + cg)*NH + h)*NW4 + w4
    const int w4 = idx % NW4;
    int t        = idx / NW4;
    const int h  = t % NH;  t /= NH;
    const int cg = t % NCG; t /= NCG;
    const int gs = t % GSPLIT;
    const int b  = t / GSPLIT;
    const int col = w4 * 4;

    const bool hm = (h > 0);
    const bool hp = (h < NH - 1);
    const bool wl = (col > 0);
    const bool wr = (col < NW - 4);

    const float* wb = wt + ((((b * NCG + cg) * 9) * NH + h) * NW + col);
    const int base  = (b * NC + (gs * GPT) * NCG + cg) * PLANE + h * NW + col;
    const float* xb = x + base;
    float* ob       = out + base;

    float4 acc[GPT];
#pragma unroll
    for (int j = 0; j < GPT; ++j)
        acc[j] = make_float4(0.f, 0.f, 0.f, 0.f);

#pragma unroll
    for (int di = 0; di < 3; ++di) {
        const bool v = (di == 1) || (di == 0 && hm) || (di == 2 && hp);
        const int roff = (di - 1) * NW;

        // ---- phase 1: batch all independent loads (3 w + 4 x) ----
        float4 w0 = *reinterpret_cast<const float4*>(wb + (di * 3 + 0) * PLANE);
        float4 w1 = *reinterpret_cast<const float4*>(wb + (di * 3 + 1) * PLANE);
        float4 w2 = *reinterpret_cast<const float4*>(wb + (di * 3 + 2) * PLANE);

        float4 xm[GPT];
#pragma unroll
        for (int j = 0; j < GPT; ++j) {
            xm[j] = make_float4(0.f, 0.f, 0.f, 0.f);
            if (v) xm[j] = *reinterpret_cast<const float4*>(xb + j * CSTRIDE + roff);
        }

        // ---- phase 2: all shuffles ----
        float xl[GPT], xr[GPT];
#pragma unroll
        for (int j = 0; j < GPT; ++j) {
            xl[j] = __shfl_up_sync(0xffffffffu,  xm[j].w, 1);
            xr[j] = __shfl_down_sync(0xffffffffu, xm[j].x, 1);
        }
#pragma unroll
        for (int j = 0; j < GPT; ++j) {
            // warp-edge lanes mid-row: real load (predicated, <=2 lanes active)
            if (lane == 0  && wl) xl[j] = v ? xb[j * CSTRIDE + roff - 1] : 0.f;
            if (lane == 31 && wr) xr[j] = v ? xb[j * CSTRIDE + roff + 4] : 0.f;
            if (!wl) xl[j] = 0.f;   // image edges: halo is zero
            if (!wr) xr[j] = 0.f;
        }

        // ---- phase 3: FMAs ----
#pragma unroll
        for (int j = 0; j < GPT; ++j) {
            // dj = -1
            acc[j].x = fmaf(xl[j],   w0.x, acc[j].x);
            acc[j].y = fmaf(xm[j].x, w0.y, acc[j].y);
            acc[j].z = fmaf(xm[j].y, w0.z, acc[j].z);
            acc[j].w = fmaf(xm[j].z, w0.w, acc[j].w);
            // dj = 0
            acc[j].x = fmaf(xm[j].x, w1.x, acc[j].x);
            acc[j].y = fmaf(xm[j].y, w1.y, acc[j].y);
            acc[j].z = fmaf(xm[j].z, w1.z, acc[j].z);
            acc[j].w = fmaf(xm[j].w, w1.w, acc[j].w);
            // dj = +1
            acc[j].x = fmaf(xm[j].y, w2.x, acc[j].x);
            acc[j].y = fmaf(xm[j].z, w2.y, acc[j].y);
            acc[j].z = fmaf(xm[j].w, w2.z, acc[j].z);
            acc[j].w = fmaf(xr[j],   w2.w, acc[j].w);
        }
    }

#pragma unroll
    for (int j = 0; j < GPT; ++j)
        __stcs(reinterpret_cast<float4*>(ob + j * CSTRIDE), acc[j]);
}

extern "C" void kernel_launch(void* const* d_in, const int* in_sizes, int n_in,
                              void* d_out, int out_size)
{
    const float* x  = (const float*)d_in[0];
    const float* wt = (const float*)d_in[1];
    float* out      = (float*)d_out;

    const int total  = NB * GSPLIT * NCG * NH * NW4; // 1605632 threads
    const int blocks = total / 128;                  // 12544
    ska_kernel<<<blocks, 128>>>(x, wt, out);
}

// round 8
// speedup vs baseline: 1.3965x; 1.0006x over previous
#include <cuda_runtime.h>

// SKA forward: out[b, g*16+cg, h, w] = sum_{k=0..8} x_pad[b, g*16+cg, h+di, w+dj] * w[b, cg, k, h, w]
// x (16,512,56,56) f32, w (16,16,9,56,56) f32, out (16,512,56,56) f32.
// R8: GPT=8 (halves per-output weight L1/L2 traffic vs GPT=4) combined with
// R7's phase batching: per di-step, load 3 w float4s, then per 4-group chunk
// batch 4 x float4 loads -> shuffles -> FMAs. ~80 regs, occupancy traded for
// MLP + fewer L1 wavefronts per output.

#define NB   16
#define NC   512
#define NG   32
#define NCG  16
#define NH   56
#define NW   56
#define NW4  14            // 56 / 4
#define PLANE   (NH * NW)  // 3136
#define GSPLIT  4
#define GPT     (NG / GSPLIT)   // 8 groups per thread
#define CHUNK   4
#define CSTRIDE (NCG * PLANE)   // stride between consecutive groups (same cg)

__global__ __launch_bounds__(128, 6) void ska_kernel(
    const float* __restrict__ x,
    const float* __restrict__ wt,
    float* __restrict__ out)
{
    const int idx = blockIdx.x * 128 + threadIdx.x;
    const int lane = threadIdx.x & 31;
    // idx = (((b*GSPLIT + gs)*NCG + cg)*NH + h)*NW4 + w4
    const int w4 = idx % NW4;
    int t        = idx / NW4;
    const int h  = t % NH;  t /= NH;
    const int cg = t % NCG; t /= NCG;
    const int gs = t % GSPLIT;
    const int b  = t / GSPLIT;
    const int col = w4 * 4;

    const bool hm = (h > 0);
    const bool hp = (h < NH - 1);
    const bool wl = (col > 0);
    const bool wr = (col < NW - 4);

    const float* wb = wt + ((((b * NCG + cg) * 9) * NH + h) * NW + col);
    const int base  = (b * NC + (gs * GPT) * NCG + cg) * PLANE + h * NW + col;
    const float* xb = x + base;
    float* ob       = out + base;

    float4 acc[GPT];
#pragma unroll
    for (int j = 0; j < GPT; ++j)
        acc[j] = make_float4(0.f, 0.f, 0.f, 0.f);

#pragma unroll
    for (int di = 0; di < 3; ++di) {
        const bool v = (di == 1) || (di == 0 && hm) || (di == 2 && hp);
        const int roff = (di - 1) * NW;

        // 3 weight float4s for this kernel row (amortized over 8 groups)
        const float4 w0 = *reinterpret_cast<const float4*>(wb + (di * 3 + 0) * PLANE);
        const float4 w1 = *reinterpret_cast<const float4*>(wb + (di * 3 + 1) * PLANE);
        const float4 w2 = *reinterpret_cast<const float4*>(wb + (di * 3 + 2) * PLANE);

#pragma unroll
        for (int jc = 0; jc < GPT; jc += CHUNK) {
            // ---- phase 1: batch CHUNK independent x loads ----
            float4 xm[CHUNK];
#pragma unroll
            for (int jj = 0; jj < CHUNK; ++jj) {
                xm[jj] = make_float4(0.f, 0.f, 0.f, 0.f);
                if (v) xm[jj] = *reinterpret_cast<const float4*>(
                                    xb + (jc + jj) * CSTRIDE + roff);
            }

            // ---- phase 2: shuffles + edge fixup ----
            float xl[CHUNK], xr[CHUNK];
#pragma unroll
            for (int jj = 0; jj < CHUNK; ++jj) {
                xl[jj] = __shfl_up_sync(0xffffffffu,  xm[jj].w, 1);
                xr[jj] = __shfl_down_sync(0xffffffffu, xm[jj].x, 1);
            }
#pragma unroll
            for (int jj = 0; jj < CHUNK; ++jj) {
                if (lane == 0  && wl) xl[jj] = v ? xb[(jc + jj) * CSTRIDE + roff - 1] : 0.f;
                if (lane == 31 && wr) xr[jj] = v ? xb[(jc + jj) * CSTRIDE + roff + 4] : 0.f;
                if (!wl) xl[jj] = 0.f;   // image edges: halo is zero
                if (!wr) xr[jj] = 0.f;
            }

            // ---- phase 3: FMAs ----
#pragma unroll
            for (int jj = 0; jj < CHUNK; ++jj) {
                const int j = jc + jj;
                // dj = -1
                acc[j].x = fmaf(xl[jj],   w0.x, acc[j].x);
                acc[j].y = fmaf(xm[jj].x, w0.y, acc[j].y);
                acc[j].z = fmaf(xm[jj].y, w0.z, acc[j].z);
                acc[j].w = fmaf(xm[jj].z, w0.w, acc[j].w);
                // dj = 0
                acc[j].x = fmaf(xm[jj].x, w1.x, acc[j].x);
                acc[j].y = fmaf(xm[jj].y, w1.y, acc[j].y);
                acc[j].z = fmaf(xm[jj].z, w1.z, acc[j].z);
                acc[j].w = fmaf(xm[jj].w, w1.w, acc[j].w);
                // dj = +1
                acc[j].x = fmaf(xm[jj].y, w2.x, acc[j].x);
                acc[j].y = fmaf(xm[jj].z, w2.y, acc[j].y);
                acc[j].z = fmaf(xm[jj].w, w2.z, acc[j].z);
                acc[j].w = fmaf(xr[jj],   w2.w, acc[j].w);
            }
        }
    }

#pragma unroll
    for (int j = 0; j < GPT; ++j)
        __stcs(reinterpret_cast<float4*>(ob + j * CSTRIDE), acc[j]);
}

extern "C" void kernel_launch(void* const* d_in, const int* in_sizes, int n_in,
                              void* d_out, int out_size)
{
    const float* x  = (const float*)d_in[0];
    const float* wt = (const float*)d_in[1];
    float* out      = (float*)d_out;

    const int total  = NB * GSPLIT * NCG * NH * NW4; // 802816 threads
    const int blocks = total / 128;                  // 6272
    ska_kernel<<<blocks, 128>>>(x, wt, out);
}